// round 8
// baseline (speedup 1.0000x reference)
#include <cuda_runtime.h>
#include <cuda_bf16.h>
#include <cstdint>

// ===========================================================================
// Problem constants
// ===========================================================================
static constexpr int B  = 16;
static constexpr int H  = 128;
static constexpr int W  = 128;
static constexpr int C  = 64;
static constexpr int NTOT = B * H * W * C;    // 16,777,216
static constexpr float DT  = 0.2f;
static constexpr float EPS = 1e-3f;

// Scratch
__device__ float d_f_buf[NTOT];               // conv1 output (f == h_init)
// Pre-split bf16 weights: [conv][ty][plane(hi=0,lo=1)*12800 + n*200 + k]
__device__ __nv_bfloat16 d_wbf[2][3][2 * 64 * 200];

// ===========================================================================
// mma.sync / ldmatrix helpers (plain-PTX, valid on .target sm_103)
// ===========================================================================
__device__ __forceinline__ uint32_t smem_u32(const void* p) {
    uint32_t a;
    asm("{ .reg .u64 t; cvta.to.shared.u64 t, %1; cvt.u32.u64 %0, t; }"
        : "=r"(a) : "l"(p));
    return a;
}

__device__ __forceinline__ void ldsm_x4(uint32_t (&r)[4], uint32_t addr) {
    asm volatile("ldmatrix.sync.aligned.m8n8.x4.shared.b16 {%0,%1,%2,%3}, [%4];"
                 : "=r"(r[0]), "=r"(r[1]), "=r"(r[2]), "=r"(r[3]) : "r"(addr));
}

__device__ __forceinline__ void mma_bf16(float (&d)[4], const uint32_t (&a)[4],
                                         uint32_t b0, uint32_t b1) {
    asm volatile(
        "mma.sync.aligned.m16n8k16.row.col.f32.bf16.bf16.f32 "
        "{%0,%1,%2,%3}, {%4,%5,%6,%7}, {%8,%9}, {%0,%1,%2,%3};"
        : "+f"(d[0]), "+f"(d[1]), "+f"(d[2]), "+f"(d[3])
        : "r"(a[0]), "r"(a[1]), "r"(a[2]), "r"(a[3]), "r"(b0), "r"(b1));
}

// ===========================================================================
// Weight prep: HWIO [3][3][64][64] -> per-ty [N=64][K=192] bf16 hi/lo split,
// rows padded to 200 bf16 (400 B).
// ===========================================================================
__global__ void prep_weights(const float* __restrict__ fw,
                             const float* __restrict__ gw)
{
    int idx = blockIdx.x * blockDim.x + threadIdx.x;     // 2*3*192*64 = 73728
    if (idx >= 73728) return;
    int conv = idx / 36864;  int r = idx - conv * 36864;
    int ty   = r / 12288;    r -= ty * 12288;
    int k    = r >> 6;       int n = r & 63;             // k 0..191, n = cout
    int tx   = k >> 6;       int ci = k & 63;
    const float* w = conv ? gw : fw;
    float v = w[(((ty * 3 + tx) * 64) + ci) * 64 + n];
    __nv_bfloat16 hi = __float2bfloat16_rn(v);
    __nv_bfloat16 lo = __float2bfloat16_rn(v - __bfloat162float(hi));
    __nv_bfloat16* base = &d_wbf[conv][ty][0];
    base[n * 200 + k]         = hi;
    base[12800 + n * 200 + k] = lo;
}

// ===========================================================================
// Conv via mma.sync bf16 (3-pass hi/lo split), fused input BN+ReLU.
// (unchanged from R7 — passing at ~190us each)
// ===========================================================================
static constexpr int A_STRIDE = 72;
static constexpr int A_PLANE  = 130 * A_STRIDE;           // 9360 bf16
static constexpr int B_PLANE  = 64 * 200;                 // 12800 bf16
static constexpr int CONV_SMEM_BYTES = (2 * A_PLANE + 2 * B_PLANE) * 2;  // 88,640

__global__ __launch_bounds__(256, 2)
void conv_mma(const float* __restrict__ in,
              const __nv_bfloat16* __restrict__ wbase,    // d_wbf[conv]
              const float* __restrict__ gamma,
              const float* __restrict__ beta,
              const float* __restrict__ mean,
              const float* __restrict__ var,
              float* __restrict__ out)
{
    extern __shared__ __align__(16) char smem_raw[];
    __nv_bfloat16* s_ah = reinterpret_cast<__nv_bfloat16*>(smem_raw);
    __nv_bfloat16* s_al = s_ah + A_PLANE;
    __nv_bfloat16* s_b  = s_al + A_PLANE;                 // [hi 12800 | lo 12800]
    __shared__ float s_scale[64], s_shift[64];

    const int tid  = threadIdx.x;
    const int wid  = tid >> 5;
    const int lane = tid & 31;
    const int y    = blockIdx.x;
    const int b    = blockIdx.y;
    const int wm   = wid & 3;
    const int wn   = wid >> 2;

    if (tid < 64) {
        float sc = gamma[tid] * rsqrtf(var[tid] + EPS);
        s_scale[tid] = sc;
        s_shift[tid] = beta[tid] - mean[tid] * sc;
    }
    __syncthreads();

    const uint32_t ah_base = smem_u32(s_ah);
    const uint32_t al_base = smem_u32(s_al);
    const uint32_t bh_base = smem_u32(s_b);
    const uint32_t bl_base = bh_base + B_PLANE * 2;

    const int r8  = lane & 7;
    const int sel = lane >> 3;
    const int a_row_off = (sel & 1) * 8 + r8;
    const int a_kh      = (sel >> 1) * 16;
    const int b_n_off   = (sel >> 1) * 8 + r8;
    const int b_kh      = (sel & 1) * 16;

    const float* inb = in + ((size_t)b * H) * W * C;

    float acc[2][4][4];
#pragma unroll
    for (int mt = 0; mt < 2; ++mt)
#pragma unroll
        for (int nt = 0; nt < 4; ++nt)
#pragma unroll
            for (int e = 0; e < 4; ++e) acc[mt][nt][e] = 0.f;

    for (int ty = 0; ty < 3; ++ty) {
        const int yy = y + ty - 1;
        const bool rowok = (unsigned)yy < (unsigned)H;
        for (int e = tid; e < 130 * 16; e += 256) {
            const int px = e >> 4;
            const int c4 = (e & 15) << 2;
            float v0 = 0.f, v1 = 0.f, v2 = 0.f, v3 = 0.f;
            if (rowok && px >= 1 && px <= 128) {
                float4 t = *reinterpret_cast<const float4*>(
                    inb + ((size_t)yy * W + (px - 1)) * C + c4);
                v0 = fmaxf(fmaf(t.x, s_scale[c4],     s_shift[c4]),     0.f);
                v1 = fmaxf(fmaf(t.y, s_scale[c4 + 1], s_shift[c4 + 1]), 0.f);
                v2 = fmaxf(fmaf(t.z, s_scale[c4 + 2], s_shift[c4 + 2]), 0.f);
                v3 = fmaxf(fmaf(t.w, s_scale[c4 + 3], s_shift[c4 + 3]), 0.f);
            }
            __nv_bfloat162 h01 = __floats2bfloat162_rn(v0, v1);
            __nv_bfloat162 h23 = __floats2bfloat162_rn(v2, v3);
            __nv_bfloat162 l01 = __floats2bfloat162_rn(
                v0 - __bfloat162float(h01.x), v1 - __bfloat162float(h01.y));
            __nv_bfloat162 l23 = __floats2bfloat162_rn(
                v2 - __bfloat162float(h23.x), v3 - __bfloat162float(h23.y));
            const int o = px * A_STRIDE + c4;
            *reinterpret_cast<__nv_bfloat162*>(s_ah + o)     = h01;
            *reinterpret_cast<__nv_bfloat162*>(s_ah + o + 2) = h23;
            *reinterpret_cast<__nv_bfloat162*>(s_al + o)     = l01;
            *reinterpret_cast<__nv_bfloat162*>(s_al + o + 2) = l23;
        }
        {
            const uint4* gsrc = reinterpret_cast<const uint4*>(wbase + ty * 2 * B_PLANE);
            uint4* dst = reinterpret_cast<uint4*>(s_b);
            for (int q = tid; q < 3200; q += 256) dst[q] = gsrc[q];
        }
        __syncthreads();

#pragma unroll
        for (int ks = 0; ks < 12; ++ks) {
            const int tx   = ks >> 2;
            const int ci16 = ks & 3;

            uint32_t afr[2][2][4];
#pragma unroll
            for (int mt = 0; mt < 2; ++mt) {
                const int px = wm * 32 + mt * 16 + a_row_off + tx;
                const uint32_t off = (uint32_t)(px * (A_STRIDE * 2) + ci16 * 32 + a_kh);
                ldsm_x4(afr[mt][0], ah_base + off);
                ldsm_x4(afr[mt][1], al_base + off);
            }
            uint32_t bfr[2][2][4];
#pragma unroll
            for (int g = 0; g < 2; ++g) {
                const int n = wn * 32 + g * 16 + b_n_off;
                const uint32_t off = (uint32_t)(n * 400 + tx * 128 + ci16 * 32 + b_kh);
                ldsm_x4(bfr[g][0], bh_base + off);
                ldsm_x4(bfr[g][1], bl_base + off);
            }
#pragma unroll
            for (int mt = 0; mt < 2; ++mt)
#pragma unroll
                for (int nt = 0; nt < 4; ++nt) {
                    const int g = nt >> 1, h2 = (nt & 1) * 2;
                    mma_bf16(acc[mt][nt], afr[mt][0], bfr[g][0][h2], bfr[g][0][h2 + 1]);
                    mma_bf16(acc[mt][nt], afr[mt][0], bfr[g][1][h2], bfr[g][1][h2 + 1]);
                    mma_bf16(acc[mt][nt], afr[mt][1], bfr[g][0][h2], bfr[g][0][h2 + 1]);
                }
        }
        __syncthreads();
    }

    float* ob = out + (((size_t)b * H + y) * W) * C;
#pragma unroll
    for (int mt = 0; mt < 2; ++mt) {
        const int x0 = wm * 32 + mt * 16 + (lane >> 2);
        float* row0 = ob + (size_t)x0 * C;
        float* row1 = row0 + 8 * C;
#pragma unroll
        for (int nt = 0; nt < 4; ++nt) {
            const int co = wn * 32 + nt * 8 + (lane & 3) * 2;
            *reinterpret_cast<float2*>(row0 + co) = make_float2(acc[mt][nt][0], acc[mt][nt][1]);
            *reinterpret_cast<float2*>(row1 + co) = make_float2(acc[mt][nt][2], acc[mt][nt][3]);
        }
    }
}

// ===========================================================================
// Fused diffusion v2: channel-pair mapping, coefficients in registers.
// 512 threads; thread owns pairs (c, c+1), c = 2*(tid&31) fixed; x = tid>>5 + 16j.
// SMEM: P0 (F / h ping), P1 (G / h pong), BX (2*DT*Dx), BY (2*DT*Dy) = 128 KB.
// Registers: hprev, hcur, E2, ax(=DT*g), cdr(=1/(1+bx+by)), cf(=2*DT*f) x 8 pairs.
// Update (exact refactor of reference):
//   s = (1-bx-by)*hprev - E2*hcur + bx*(hxm+hxp) + ax*(hxp-hxm)
//     + by*(hcm+hcp) + ax*(hcp-hcm) + cf ;  s *= cdr
// where for elem c:  hcp = hcur.y (own reg);  for elem c+1: hcm = hcur.x (own reg).
// ===========================================================================
static constexpr int DIFF_SMEM_BYTES = 4 * 8192 * 4;   // 131,072 B

__global__ __launch_bounds__(512, 1)
void diffuse_fused(const float* __restrict__ f,
                   float* __restrict__ outh,
                   const float* __restrict__ g,
                   const float* __restrict__ gamma,
                   const float* __restrict__ beta,
                   const float* __restrict__ mean,
                   const float* __restrict__ var)
{
    extern __shared__ float sm[];
    float* P0 = sm;              // F, then h ping (rb for even k)
    float* P1 = sm + 8192;       // G, then h pong
    float* BX = sm + 16384;      // 2*DT*Dx
    float* BY = sm + 24576;      // 2*DT*Dy
    __shared__ float sc[64], sh[64];

    const int tid = threadIdx.x;
    const int y   = blockIdx.x;
    const int b   = blockIdx.y;

    if (tid < 64) {
        float s = gamma[tid] * rsqrtf(var[tid] + EPS);
        sc[tid] = s;
        sh[tid] = beta[tid] - mean[tid] * s;
    }

    const size_t rowbase = (((size_t)b * H) + y) * W * C;
    const float* frow = f + rowbase;
    const float* grow = g + rowbase;
#pragma unroll
    for (int q = 0; q < 4; ++q) {
        const int idx = (tid + q * 512) * 4;
        *reinterpret_cast<float4*>(P0 + idx) = *reinterpret_cast<const float4*>(frow + idx);
        *reinterpret_cast<float4*>(P1 + idx) = *reinterpret_cast<const float4*>(grow + idx);
    }
    __syncthreads();

    const int c = (tid & 31) * 2;              // fixed channel pair (c, c+1)
    const float2 sc2 = make_float2(sc[c], sc[c + 1]);
    const float2 sh2 = make_float2(sh[c], sh[c + 1]);

    const int ym = (y == 0) ? 1 : y - 1;
    const int yp = (y == H - 1) ? H - 2 : y + 1;
    const float* fm = f + ((((size_t)b * H) + ym) * W) * C;
    const float* fp = f + ((((size_t)b * H) + yp) * W) * C;

    float2 hprev[8], hcur[8], E2r[8], axr[8], cdr[8], cfr[8];

    // ---- setup: Sobel + all coefficients (reads P0=F, P1=G; writes BX,BY own) ----
#pragma unroll
    for (int j = 0; j < 8; ++j) {
        const int i = (tid + j * 512) * 2;
        const int x = i >> 6;
        const int xm = (x == 0) ? 1 : x - 1;
        const int xp = (x == W - 1) ? W - 2 : x + 1;

        const float2 f2 = *reinterpret_cast<const float2*>(P0 + i);
        const float2 g2 = *reinterpret_cast<const float2*>(P1 + i);

        const float2 am = *reinterpret_cast<const float2*>(fm + xm * 64 + c);
        const float2 a0 = *reinterpret_cast<const float2*>(fm + x  * 64 + c);
        const float2 ap = *reinterpret_cast<const float2*>(fm + xp * 64 + c);
        const float2 bm = *reinterpret_cast<const float2*>(fp + xm * 64 + c);
        const float2 b0 = *reinterpret_cast<const float2*>(fp + x  * 64 + c);
        const float2 bp = *reinterpret_cast<const float2*>(fp + xp * 64 + c);
        const float2 fxm = *reinterpret_cast<const float2*>(P0 + xm * 64 + c);
        const float2 fxp = *reinterpret_cast<const float2*>(P0 + xp * 64 + c);

        float dyx = (bm.x + 2.f * b0.x + bp.x) - (am.x + 2.f * a0.x + ap.x);
        float dyy = (bm.y + 2.f * b0.y + bp.y) - (am.y + 2.f * a0.y + ap.y);
        float dxx = (ap.x - am.x) + 2.f * (fxp.x - fxm.x) + (bp.x - bm.x);
        float dxy = (ap.y - am.y) + 2.f * (fxp.y - fxm.y) + (bp.y - bm.y);

        float bxx = (2.f * DT) / (0.25f * dyx * dyx + 1.f);
        float bxy = (2.f * DT) / (0.25f * dyy * dyy + 1.f);
        float byx = (2.f * DT) / (0.25f * dxx * dxx + 1.f);
        float byy = (2.f * DT) / (0.25f * dxy * dxy + 1.f);
        *reinterpret_cast<float2*>(BX + i) = make_float2(bxx, bxy);
        *reinterpret_cast<float2*>(BY + i) = make_float2(byx, byy);

        cdr[j] = make_float2(1.f / (1.f + bxx + byx), 1.f / (1.f + bxy + byy));
        axr[j] = make_float2(DT * g2.x, DT * g2.y);
        cfr[j] = make_float2(2.f * DT * f2.x, 2.f * DT * f2.y);
        hprev[j] = f2;
        hcur[j]  = f2;

        // E2 = 2*E = DT*((g[x-1]-g[x+1]) + (g[c-1]-g[c+1]))  (P1 still == G here)
        const int ixm = (i + 8192 - 64) & 8191;
        const int ixp = (i + 64) & 8191;
        const float2 gxm = *reinterpret_cast<const float2*>(P1 + ixm);
        const float2 gxp = *reinterpret_cast<const float2*>(P1 + ixp);
        const float gcm = P1[(i & ~63) | ((c + 63) & 63)];
        const float gcp = P1[(i & ~63) | ((c + 2) & 63)];
        E2r[j].x = DT * ((gxm.x - gxp.x) + (gcm - g2.y));
        E2r[j].y = DT * ((gxm.y - gxp.y) + (g2.x - gcp));
    }
    __syncthreads();

    // ---- K = 5 iterations ----
#pragma unroll
    for (int k = 0; k < 5; ++k) {
        float* rb = (k & 1) ? P1 : P0;
        float* wb = (k & 1) ? P0 : P1;
#pragma unroll
        for (int j = 0; j < 8; ++j) {
            const int i = (tid + j * 512) * 2;
            const int ixm = (i + 8192 - 64) & 8191;
            const int ixp = (i + 64) & 8191;
            const float2 bx2 = *reinterpret_cast<const float2*>(BX + i);
            const float2 by2 = *reinterpret_cast<const float2*>(BY + i);
            const float2 rxm = *reinterpret_cast<const float2*>(rb + ixm);
            const float2 rxp = *reinterpret_cast<const float2*>(rb + ixp);
            const float rcm = rb[(i & ~63) | ((c + 63) & 63)];   // h[c-1]
            const float rcp = rb[(i & ~63) | ((c + 2) & 63)];    // h[c+2]
            const float2 hc = hcur[j];
            const float2 ax = axr[j];

            float s0 = (1.f - bx2.x - by2.x) * hprev[j].x;
            s0 = fmaf(-E2r[j].x, hc.x, s0);
            s0 = fmaf(bx2.x, rxm.x + rxp.x, s0);
            s0 = fmaf(ax.x,  rxp.x - rxm.x, s0);
            s0 = fmaf(by2.x, rcm + hc.y, s0);
            s0 = fmaf(ax.x,  hc.y - rcm, s0);
            s0 = (s0 + cfr[j].x) * cdr[j].x;

            float s1 = (1.f - bx2.y - by2.y) * hprev[j].y;
            s1 = fmaf(-E2r[j].y, hc.y, s1);
            s1 = fmaf(bx2.y, rxm.y + rxp.y, s1);
            s1 = fmaf(ax.y,  rxp.y - rxm.y, s1);
            s1 = fmaf(by2.y, hc.x + rcp, s1);
            s1 = fmaf(ax.y,  rcp - hc.x, s1);
            s1 = (s1 + cfr[j].y) * cdr[j].y;

            hprev[j] = hc;
            hcur[j]  = make_float2(s0, s1);
            if (k < 4) *reinterpret_cast<float2*>(wb + i) = hcur[j];
        }
        if (k < 4) __syncthreads();
    }

    // ---- epilogue: relu(bn_o(h)) from registers ----
    float* o = outh + rowbase;
#pragma unroll
    for (int j = 0; j < 8; ++j) {
        const int i = (tid + j * 512) * 2;
        float2 r = make_float2(fmaxf(fmaf(hcur[j].x, sc2.x, sh2.x), 0.f),
                               fmaxf(fmaf(hcur[j].y, sc2.y, sh2.y), 0.f));
        *reinterpret_cast<float2*>(o + i) = r;
    }
}

// ===========================================================================
extern "C" void kernel_launch(void* const* d_in, const int* in_sizes, int n_in,
                              void* d_out, int out_size)
{
    const float* x   = (const float*)d_in[0];
    const float* f_w = (const float*)d_in[1];
    const float* g_w = (const float*)d_in[2];
    const float* bnf_gamma = (const float*)d_in[3];
    const float* bnf_beta  = (const float*)d_in[4];
    const float* bnf_mean  = (const float*)d_in[5];
    const float* bnf_var   = (const float*)d_in[6];
    const float* bng_gamma = (const float*)d_in[7];
    const float* bng_beta  = (const float*)d_in[8];
    const float* bng_mean  = (const float*)d_in[9];
    const float* bng_var   = (const float*)d_in[10];
    const float* bno_gamma = (const float*)d_in[11];
    const float* bno_beta  = (const float*)d_in[12];
    const float* bno_mean  = (const float*)d_in[13];
    const float* bno_var   = (const float*)d_in[14];

    float* out = (float*)d_out;            // [0:N) = h, [N:2N) = g

    float* fptr = nullptr;
    cudaGetSymbolAddress((void**)&fptr, d_f_buf);
    __nv_bfloat16* wptr = nullptr;
    cudaGetSymbolAddress((void**)&wptr, d_wbf);

    cudaFuncSetAttribute(conv_mma,
                         cudaFuncAttributeMaxDynamicSharedMemorySize, CONV_SMEM_BYTES);
    cudaFuncSetAttribute(diffuse_fused,
                         cudaFuncAttributeMaxDynamicSharedMemorySize, DIFF_SMEM_BYTES);

    // 1) weight transform (both convs)
    prep_weights<<<288, 256>>>(f_w, g_w);

    dim3 grid(H, B);

    // 2) f = conv(relu(bn_f(x)), f_w)
    conv_mma<<<grid, 256, CONV_SMEM_BYTES>>>(
        x, wptr, bnf_gamma, bnf_beta, bnf_mean, bnf_var, fptr);

    // 3) g = conv(relu(bn_g(f)), g_w) -> d_out[N:2N)
    conv_mma<<<grid, 256, CONV_SMEM_BYTES>>>(
        fptr, wptr + 3 * 2 * 64 * 200, bng_gamma, bng_beta, bng_mean, bng_var, out + NTOT);

    // 4) fused sobel + coefficients + 5 diffusion iters + bn_o/relu -> d_out[0:N)
    diffuse_fused<<<grid, 512, DIFF_SMEM_BYTES>>>(
        fptr, out, out + NTOT, bno_gamma, bno_beta, bno_mean, bno_var);
}

// round 9
// speedup vs baseline: 1.4822x; 1.4822x over previous
#include <cuda_runtime.h>
#include <cuda_bf16.h>
#include <cstdint>

// ===========================================================================
// Problem constants
// ===========================================================================
static constexpr int B  = 16;
static constexpr int H  = 128;
static constexpr int W  = 128;
static constexpr int C  = 64;
static constexpr int NTOT = B * H * W * C;    // 16,777,216
static constexpr float DT  = 0.2f;
static constexpr float EPS = 1e-3f;

// Scratch
__device__ float d_f_buf[NTOT];               // conv1 output (f == h_init)
// Pre-split bf16 weights: [conv][ty][plane(hi=0,lo=1)*12800 + n*200 + k]
__device__ __nv_bfloat16 d_wbf[2][3][2 * 64 * 200];

// ===========================================================================
// PTX helpers (plain-PTX, valid on .target sm_103)
// ===========================================================================
__device__ __forceinline__ uint32_t smem_u32(const void* p) {
    uint32_t a;
    asm("{ .reg .u64 t; cvta.to.shared.u64 t, %1; cvt.u32.u64 %0, t; }"
        : "=r"(a) : "l"(p));
    return a;
}

__device__ __forceinline__ void ldsm_x4(uint32_t (&r)[4], uint32_t addr) {
    asm volatile("ldmatrix.sync.aligned.m8n8.x4.shared.b16 {%0,%1,%2,%3}, [%4];"
                 : "=r"(r[0]), "=r"(r[1]), "=r"(r[2]), "=r"(r[3]) : "r"(addr));
}

__device__ __forceinline__ void mma_bf16(float (&d)[4], const uint32_t (&a)[4],
                                         uint32_t b0, uint32_t b1) {
    asm volatile(
        "mma.sync.aligned.m16n8k16.row.col.f32.bf16.bf16.f32 "
        "{%0,%1,%2,%3}, {%4,%5,%6,%7}, {%8,%9}, {%0,%1,%2,%3};"
        : "+f"(d[0]), "+f"(d[1]), "+f"(d[2]), "+f"(d[3])
        : "r"(a[0]), "r"(a[1]), "r"(a[2]), "r"(a[3]), "r"(b0), "r"(b1));
}

__device__ __forceinline__ void cp_async16(uint32_t saddr, const void* gaddr) {
    asm volatile("cp.async.cg.shared.global [%0], [%1], 16;"
                 :: "r"(saddr), "l"(gaddr) : "memory");
}
__device__ __forceinline__ void cp_commit() {
    asm volatile("cp.async.commit_group;" ::: "memory");
}
template <int N>
__device__ __forceinline__ void cp_wait() {
    asm volatile("cp.async.wait_group %0;" :: "n"(N) : "memory");
}

// ===========================================================================
// Weight prep: HWIO [3][3][64][64] -> per-ty [N=64][K=192] bf16 hi/lo split,
// rows padded to 200 bf16 (400 B).
// ===========================================================================
__global__ void prep_weights(const float* __restrict__ fw,
                             const float* __restrict__ gw)
{
    int idx = blockIdx.x * blockDim.x + threadIdx.x;     // 2*3*192*64 = 73728
    if (idx >= 73728) return;
    int conv = idx / 36864;  int r = idx - conv * 36864;
    int ty   = r / 12288;    r -= ty * 12288;
    int k    = r >> 6;       int n = r & 63;             // k 0..191, n = cout
    int tx   = k >> 6;       int ci = k & 63;
    const float* w = conv ? gw : fw;
    float v = w[(((ty * 3 + tx) * 64) + ci) * 64 + n];
    __nv_bfloat16 hi = __float2bfloat16_rn(v);
    __nv_bfloat16 lo = __float2bfloat16_rn(v - __bfloat162float(hi));
    __nv_bfloat16* base = &d_wbf[conv][ty][0];
    base[n * 200 + k]         = hi;
    base[12800 + n * 200 + k] = lo;
}

// ===========================================================================
// Conv v2: mma.sync bf16 3-pass, software-pipelined staging.
//  - All 3 ty weight planes resident in smem, fetched via cp.async groups
//    (group ty waited right before its mma use -> latency hidden under mma).
//  - A row for ty+1 prefetched into registers during mma(ty); transformed
//    (BN+ReLU+hi/lo split) into the single A buffer after mma completes.
// SMEM: A [2 planes][130*72] = 37,440 B ; B [3 ty][2 planes][64*200] = 153,600 B
// ===========================================================================
static constexpr int A_STRIDE = 72;
static constexpr int A_PLANE  = 130 * A_STRIDE;           // 9360 bf16
static constexpr int B_PLANE  = 64 * 200;                 // 12800 bf16
static constexpr int B_TY     = 2 * B_PLANE;              // 25600 bf16 per ty
static constexpr int CONV_SMEM_BYTES = (2 * A_PLANE + 3 * B_TY) * 2;  // 191,040

__global__ __launch_bounds__(256, 1)
void conv_mma(const float* __restrict__ in,
              const __nv_bfloat16* __restrict__ wbase,    // d_wbf[conv]
              const float* __restrict__ gamma,
              const float* __restrict__ beta,
              const float* __restrict__ mean,
              const float* __restrict__ var,
              float* __restrict__ out)
{
    extern __shared__ __align__(16) char smem_raw[];
    __nv_bfloat16* s_ah = reinterpret_cast<__nv_bfloat16*>(smem_raw);
    __nv_bfloat16* s_al = s_ah + A_PLANE;
    __nv_bfloat16* s_b  = s_al + A_PLANE;                 // [3 ty][hi|lo]
    __shared__ float s_scale[64], s_shift[64];

    const int tid  = threadIdx.x;
    const int wid  = tid >> 5;
    const int lane = tid & 31;
    const int y    = blockIdx.x;
    const int b    = blockIdx.y;
    const int wm   = wid & 3;
    const int wn   = wid >> 2;

    if (tid < 64) {
        float sc = gamma[tid] * rsqrtf(var[tid] + EPS);
        s_scale[tid] = sc;
        s_shift[tid] = beta[tid] - mean[tid] * sc;
    }

    const uint32_t ah_base = smem_u32(s_ah);
    const uint32_t al_base = smem_u32(s_al);
    const uint32_t b_base  = smem_u32(s_b);

    // ---- issue cp.async for all 3 weight groups (one commit group per ty) ----
    {
        const uint32_t sb0 = b_base;
#pragma unroll
        for (int tyg = 0; tyg < 3; ++tyg) {
            const char* src = reinterpret_cast<const char*>(wbase + tyg * B_TY);
            const uint32_t dst = sb0 + (uint32_t)tyg * (B_TY * 2);
#pragma unroll
            for (int q = 0; q < 13; ++q) {
                int idx = tid + q * 256;
                if (idx < 3200) cp_async16(dst + idx * 16, src + idx * 16);
            }
            cp_commit();
        }
    }

    const float* inb = in + ((size_t)b * H) * W * C;

    // per-thread A staging decode (fixed across rows)
    // e = tid + q*256 covers 130*16 = 2080 float4 slots
    const int r8  = lane & 7;
    const int sel = lane >> 3;
    const int a_row_off = (sel & 1) * 8 + r8;
    const int a_kh      = (sel >> 1) * 16;
    const int b_n_off   = (sel >> 1) * 8 + r8;
    const int b_kh      = (sel & 1) * 16;

    float4 pr[9];

    // ---- prefetch A row for ty=0 (input row y-1) ----
    {
        const int yy = y - 1;
        const bool rowok = (unsigned)yy < (unsigned)H;
#pragma unroll
        for (int q = 0; q < 9; ++q) {
            const int e = tid + q * 256;
            pr[q] = make_float4(0.f, 0.f, 0.f, 0.f);
            if (e < 2080) {
                const int px = e >> 4;
                const int c4 = (e & 15) << 2;
                if (rowok && px >= 1 && px <= 128)
                    pr[q] = *reinterpret_cast<const float4*>(
                        inb + ((size_t)yy * W + (px - 1)) * C + c4);
            }
        }
    }
    __syncthreads();   // s_scale/s_shift ready

    // ---- transform A(ty=0) -> smem buffer ----
    {
        const int yy = y - 1;
        const bool rowok = (unsigned)yy < (unsigned)H;
#pragma unroll
        for (int q = 0; q < 9; ++q) {
            const int e = tid + q * 256;
            if (e >= 2080) break;
            const int px = e >> 4;
            const int c4 = (e & 15) << 2;
            float v0 = 0.f, v1 = 0.f, v2 = 0.f, v3 = 0.f;
            if (rowok && px >= 1 && px <= 128) {
                v0 = fmaxf(fmaf(pr[q].x, s_scale[c4],     s_shift[c4]),     0.f);
                v1 = fmaxf(fmaf(pr[q].y, s_scale[c4 + 1], s_shift[c4 + 1]), 0.f);
                v2 = fmaxf(fmaf(pr[q].z, s_scale[c4 + 2], s_shift[c4 + 2]), 0.f);
                v3 = fmaxf(fmaf(pr[q].w, s_scale[c4 + 3], s_shift[c4 + 3]), 0.f);
            }
            __nv_bfloat162 h01 = __floats2bfloat162_rn(v0, v1);
            __nv_bfloat162 h23 = __floats2bfloat162_rn(v2, v3);
            __nv_bfloat162 l01 = __floats2bfloat162_rn(
                v0 - __bfloat162float(h01.x), v1 - __bfloat162float(h01.y));
            __nv_bfloat162 l23 = __floats2bfloat162_rn(
                v2 - __bfloat162float(h23.x), v3 - __bfloat162float(h23.y));
            const int o = px * A_STRIDE + c4;
            *reinterpret_cast<__nv_bfloat162*>(s_ah + o)     = h01;
            *reinterpret_cast<__nv_bfloat162*>(s_ah + o + 2) = h23;
            *reinterpret_cast<__nv_bfloat162*>(s_al + o)     = l01;
            *reinterpret_cast<__nv_bfloat162*>(s_al + o + 2) = l23;
        }
    }
    cp_wait<2>();      // B[0] arrived
    __syncthreads();

    float acc[2][4][4];
#pragma unroll
    for (int mt = 0; mt < 2; ++mt)
#pragma unroll
        for (int nt = 0; nt < 4; ++nt)
#pragma unroll
            for (int e = 0; e < 4; ++e) acc[mt][nt][e] = 0.f;

#pragma unroll
    for (int ty = 0; ty < 3; ++ty) {
        // ---- prefetch A row for ty+1 (input row y+ty) into registers ----
        if (ty < 2) {
            const int yy = y + ty;
            const bool rowok = (unsigned)yy < (unsigned)H;   // always true here, but keep
#pragma unroll
            for (int q = 0; q < 9; ++q) {
                const int e = tid + q * 256;
                pr[q] = make_float4(0.f, 0.f, 0.f, 0.f);
                if (e < 2080) {
                    const int px = e >> 4;
                    const int c4 = (e & 15) << 2;
                    if (rowok && px >= 1 && px <= 128)
                        pr[q] = *reinterpret_cast<const float4*>(
                            inb + ((size_t)yy * W + (px - 1)) * C + c4);
                }
            }
        }

        // ---- mma over this ty's 12 k-steps ----
        const uint32_t bh_base = b_base + (uint32_t)ty * (B_TY * 2);
        const uint32_t bl_base = bh_base + B_PLANE * 2;
#pragma unroll
        for (int ks = 0; ks < 12; ++ks) {
            const int tx   = ks >> 2;
            const int ci16 = ks & 3;

            uint32_t afr[2][2][4];
#pragma unroll
            for (int mt = 0; mt < 2; ++mt) {
                const int px = wm * 32 + mt * 16 + a_row_off + tx;
                const uint32_t off = (uint32_t)(px * (A_STRIDE * 2) + ci16 * 32 + a_kh);
                ldsm_x4(afr[mt][0], ah_base + off);
                ldsm_x4(afr[mt][1], al_base + off);
            }
            uint32_t bfr[2][2][4];
#pragma unroll
            for (int g = 0; g < 2; ++g) {
                const int n = wn * 32 + g * 16 + b_n_off;
                const uint32_t off = (uint32_t)(n * 400 + tx * 128 + ci16 * 32 + b_kh);
                ldsm_x4(bfr[g][0], bh_base + off);
                ldsm_x4(bfr[g][1], bl_base + off);
            }
#pragma unroll
            for (int mt = 0; mt < 2; ++mt)
#pragma unroll
                for (int nt = 0; nt < 4; ++nt) {
                    const int g = nt >> 1, h2 = (nt & 1) * 2;
                    mma_bf16(acc[mt][nt], afr[mt][0], bfr[g][0][h2], bfr[g][0][h2 + 1]);
                    mma_bf16(acc[mt][nt], afr[mt][0], bfr[g][1][h2], bfr[g][1][h2 + 1]);
                    mma_bf16(acc[mt][nt], afr[mt][1], bfr[g][0][h2], bfr[g][0][h2 + 1]);
                }
        }

        // ---- transform prefetched regs into the A buffer for next ty ----
        if (ty < 2) {
            __syncthreads();          // everyone done reading A(ty)
            const int yy = y + ty;
            const bool rowok = (unsigned)yy < (unsigned)H;
#pragma unroll
            for (int q = 0; q < 9; ++q) {
                const int e = tid + q * 256;
                if (e >= 2080) break;
                const int px = e >> 4;
                const int c4 = (e & 15) << 2;
                float v0 = 0.f, v1 = 0.f, v2 = 0.f, v3 = 0.f;
                if (rowok && px >= 1 && px <= 128) {
                    v0 = fmaxf(fmaf(pr[q].x, s_scale[c4],     s_shift[c4]),     0.f);
                    v1 = fmaxf(fmaf(pr[q].y, s_scale[c4 + 1], s_shift[c4 + 1]), 0.f);
                    v2 = fmaxf(fmaf(pr[q].z, s_scale[c4 + 2], s_shift[c4 + 2]), 0.f);
                    v3 = fmaxf(fmaf(pr[q].w, s_scale[c4 + 3], s_shift[c4 + 3]), 0.f);
                }
                __nv_bfloat162 h01 = __floats2bfloat162_rn(v0, v1);
                __nv_bfloat162 h23 = __floats2bfloat162_rn(v2, v3);
                __nv_bfloat162 l01 = __floats2bfloat162_rn(
                    v0 - __bfloat162float(h01.x), v1 - __bfloat162float(h01.y));
                __nv_bfloat162 l23 = __floats2bfloat162_rn(
                    v2 - __bfloat162float(h23.x), v3 - __bfloat162float(h23.y));
                const int o = px * A_STRIDE + c4;
                *reinterpret_cast<__nv_bfloat162*>(s_ah + o)     = h01;
                *reinterpret_cast<__nv_bfloat162*>(s_ah + o + 2) = h23;
                *reinterpret_cast<__nv_bfloat162*>(s_al + o)     = l01;
                *reinterpret_cast<__nv_bfloat162*>(s_al + o + 2) = l23;
            }
            if (ty == 0) cp_wait<1>();   // B[1] arrived
            else         cp_wait<0>();   // B[2] arrived
            __syncthreads();
        }
    }

    // ---- epilogue: fp32 accumulators -> NHWC output ----
    float* ob = out + (((size_t)b * H + y) * W) * C;
#pragma unroll
    for (int mt = 0; mt < 2; ++mt) {
        const int x0 = wm * 32 + mt * 16 + (lane >> 2);
        float* row0 = ob + (size_t)x0 * C;
        float* row1 = row0 + 8 * C;
#pragma unroll
        for (int nt = 0; nt < 4; ++nt) {
            const int co = wn * 32 + nt * 8 + (lane & 3) * 2;
            *reinterpret_cast<float2*>(row0 + co) = make_float2(acc[mt][nt][0], acc[mt][nt][1]);
            *reinterpret_cast<float2*>(row1 + co) = make_float2(acc[mt][nt][2], acc[mt][nt][3]);
        }
    }
}

// ===========================================================================
// Fused diffusion (R8 version): channel-pair mapping, coefficients in regs.
// ===========================================================================
static constexpr int DIFF_SMEM_BYTES = 4 * 8192 * 4;   // 131,072 B

__global__ __launch_bounds__(512, 1)
void diffuse_fused(const float* __restrict__ f,
                   float* __restrict__ outh,
                   const float* __restrict__ g,
                   const float* __restrict__ gamma,
                   const float* __restrict__ beta,
                   const float* __restrict__ mean,
                   const float* __restrict__ var)
{
    extern __shared__ float sm[];
    float* P0 = sm;              // F, then h ping
    float* P1 = sm + 8192;       // G, then h pong
    float* BX = sm + 16384;      // 2*DT*Dx
    float* BY = sm + 24576;      // 2*DT*Dy
    __shared__ float sc[64], sh[64];

    const int tid = threadIdx.x;
    const int y   = blockIdx.x;
    const int b   = blockIdx.y;

    if (tid < 64) {
        float s = gamma[tid] * rsqrtf(var[tid] + EPS);
        sc[tid] = s;
        sh[tid] = beta[tid] - mean[tid] * s;
    }

    const size_t rowbase = (((size_t)b * H) + y) * W * C;
    const float* frow = f + rowbase;
    const float* grow = g + rowbase;
#pragma unroll
    for (int q = 0; q < 4; ++q) {
        const int idx = (tid + q * 512) * 4;
        *reinterpret_cast<float4*>(P0 + idx) = *reinterpret_cast<const float4*>(frow + idx);
        *reinterpret_cast<float4*>(P1 + idx) = *reinterpret_cast<const float4*>(grow + idx);
    }
    __syncthreads();

    const int c = (tid & 31) * 2;
    const float2 sc2 = make_float2(sc[c], sc[c + 1]);
    const float2 sh2 = make_float2(sh[c], sh[c + 1]);

    const int ym = (y == 0) ? 1 : y - 1;
    const int yp = (y == H - 1) ? H - 2 : y + 1;
    const float* fm = f + ((((size_t)b * H) + ym) * W) * C;
    const float* fp = f + ((((size_t)b * H) + yp) * W) * C;

    float2 hprev[8], hcur[8], E2r[8], axr[8], cdr[8], cfr[8];

#pragma unroll
    for (int j = 0; j < 8; ++j) {
        const int i = (tid + j * 512) * 2;
        const int x = i >> 6;
        const int xm = (x == 0) ? 1 : x - 1;
        const int xp = (x == W - 1) ? W - 2 : x + 1;

        const float2 f2 = *reinterpret_cast<const float2*>(P0 + i);
        const float2 g2 = *reinterpret_cast<const float2*>(P1 + i);

        const float2 am = *reinterpret_cast<const float2*>(fm + xm * 64 + c);
        const float2 a0 = *reinterpret_cast<const float2*>(fm + x  * 64 + c);
        const float2 ap = *reinterpret_cast<const float2*>(fm + xp * 64 + c);
        const float2 bm = *reinterpret_cast<const float2*>(fp + xm * 64 + c);
        const float2 b0 = *reinterpret_cast<const float2*>(fp + x  * 64 + c);
        const float2 bp = *reinterpret_cast<const float2*>(fp + xp * 64 + c);
        const float2 fxm = *reinterpret_cast<const float2*>(P0 + xm * 64 + c);
        const float2 fxp = *reinterpret_cast<const float2*>(P0 + xp * 64 + c);

        float dyx = (bm.x + 2.f * b0.x + bp.x) - (am.x + 2.f * a0.x + ap.x);
        float dyy = (bm.y + 2.f * b0.y + bp.y) - (am.y + 2.f * a0.y + ap.y);
        float dxx = (ap.x - am.x) + 2.f * (fxp.x - fxm.x) + (bp.x - bm.x);
        float dxy = (ap.y - am.y) + 2.f * (fxp.y - fxm.y) + (bp.y - bm.y);

        float bxx = (2.f * DT) / (0.25f * dyx * dyx + 1.f);
        float bxy = (2.f * DT) / (0.25f * dyy * dyy + 1.f);
        float byx = (2.f * DT) / (0.25f * dxx * dxx + 1.f);
        float byy = (2.f * DT) / (0.25f * dxy * dxy + 1.f);
        *reinterpret_cast<float2*>(BX + i) = make_float2(bxx, bxy);
        *reinterpret_cast<float2*>(BY + i) = make_float2(byx, byy);

        cdr[j] = make_float2(1.f / (1.f + bxx + byx), 1.f / (1.f + bxy + byy));
        axr[j] = make_float2(DT * g2.x, DT * g2.y);
        cfr[j] = make_float2(2.f * DT * f2.x, 2.f * DT * f2.y);
        hprev[j] = f2;
        hcur[j]  = f2;

        const int ixm = (i + 8192 - 64) & 8191;
        const int ixp = (i + 64) & 8191;
        const float2 gxm = *reinterpret_cast<const float2*>(P1 + ixm);
        const float2 gxp = *reinterpret_cast<const float2*>(P1 + ixp);
        const float gcm = P1[(i & ~63) | ((c + 63) & 63)];
        const float gcp = P1[(i & ~63) | ((c + 2) & 63)];
        E2r[j].x = DT * ((gxm.x - gxp.x) + (gcm - g2.y));
        E2r[j].y = DT * ((gxm.y - gxp.y) + (g2.x - gcp));
    }
    __syncthreads();

#pragma unroll
    for (int k = 0; k < 5; ++k) {
        float* rb = (k & 1) ? P1 : P0;
        float* wb = (k & 1) ? P0 : P1;
#pragma unroll
        for (int j = 0; j < 8; ++j) {
            const int i = (tid + j * 512) * 2;
            const int ixm = (i + 8192 - 64) & 8191;
            const int ixp = (i + 64) & 8191;
            const float2 bx2 = *reinterpret_cast<const float2*>(BX + i);
            const float2 by2 = *reinterpret_cast<const float2*>(BY + i);
            const float2 rxm = *reinterpret_cast<const float2*>(rb + ixm);
            const float2 rxp = *reinterpret_cast<const float2*>(rb + ixp);
            const float rcm = rb[(i & ~63) | ((c + 63) & 63)];
            const float rcp = rb[(i & ~63) | ((c + 2) & 63)];
            const float2 hc = hcur[j];
            const float2 ax = axr[j];

            float s0 = (1.f - bx2.x - by2.x) * hprev[j].x;
            s0 = fmaf(-E2r[j].x, hc.x, s0);
            s0 = fmaf(bx2.x, rxm.x + rxp.x, s0);
            s0 = fmaf(ax.x,  rxp.x - rxm.x, s0);
            s0 = fmaf(by2.x, rcm + hc.y, s0);
            s0 = fmaf(ax.x,  hc.y - rcm, s0);
            s0 = (s0 + cfr[j].x) * cdr[j].x;

            float s1 = (1.f - bx2.y - by2.y) * hprev[j].y;
            s1 = fmaf(-E2r[j].y, hc.y, s1);
            s1 = fmaf(bx2.y, rxm.y + rxp.y, s1);
            s1 = fmaf(ax.y,  rxp.y - rxm.y, s1);
            s1 = fmaf(by2.y, hc.x + rcp, s1);
            s1 = fmaf(ax.y,  rcp - hc.x, s1);
            s1 = (s1 + cfr[j].y) * cdr[j].y;

            hprev[j] = hc;
            hcur[j]  = make_float2(s0, s1);
            if (k < 4) *reinterpret_cast<float2*>(wb + i) = hcur[j];
        }
        if (k < 4) __syncthreads();
    }

    float* o = outh + rowbase;
#pragma unroll
    for (int j = 0; j < 8; ++j) {
        const int i = (tid + j * 512) * 2;
        float2 r = make_float2(fmaxf(fmaf(hcur[j].x, sc2.x, sh2.x), 0.f),
                               fmaxf(fmaf(hcur[j].y, sc2.y, sh2.y), 0.f));
        *reinterpret_cast<float2*>(o + i) = r;
    }
}

// ===========================================================================
extern "C" void kernel_launch(void* const* d_in, const int* in_sizes, int n_in,
                              void* d_out, int out_size)
{
    const float* x   = (const float*)d_in[0];
    const float* f_w = (const float*)d_in[1];
    const float* g_w = (const float*)d_in[2];
    const float* bnf_gamma = (const float*)d_in[3];
    const float* bnf_beta  = (const float*)d_in[4];
    const float* bnf_mean  = (const float*)d_in[5];
    const float* bnf_var   = (const float*)d_in[6];
    const float* bng_gamma = (const float*)d_in[7];
    const float* bng_beta  = (const float*)d_in[8];
    const float* bng_mean  = (const float*)d_in[9];
    const float* bng_var   = (const float*)d_in[10];
    const float* bno_gamma = (const float*)d_in[11];
    const float* bno_beta  = (const float*)d_in[12];
    const float* bno_mean  = (const float*)d_in[13];
    const float* bno_var   = (const float*)d_in[14];

    float* out = (float*)d_out;            // [0:N) = h, [N:2N) = g

    float* fptr = nullptr;
    cudaGetSymbolAddress((void**)&fptr, d_f_buf);
    __nv_bfloat16* wptr = nullptr;
    cudaGetSymbolAddress((void**)&wptr, d_wbf);

    cudaFuncSetAttribute(conv_mma,
                         cudaFuncAttributeMaxDynamicSharedMemorySize, CONV_SMEM_BYTES);
    cudaFuncSetAttribute(diffuse_fused,
                         cudaFuncAttributeMaxDynamicSharedMemorySize, DIFF_SMEM_BYTES);

    // 1) weight transform (both convs)
    prep_weights<<<288, 256>>>(f_w, g_w);

    dim3 grid(H, B);

    // 2) f = conv(relu(bn_f(x)), f_w)
    conv_mma<<<grid, 256, CONV_SMEM_BYTES>>>(
        x, wptr, bnf_gamma, bnf_beta, bnf_mean, bnf_var, fptr);

    // 3) g = conv(relu(bn_g(f)), g_w) -> d_out[N:2N)
    conv_mma<<<grid, 256, CONV_SMEM_BYTES>>>(
        fptr, wptr + 3 * B_TY, bng_gamma, bng_beta, bng_mean, bng_var, out + NTOT);

    // 4) fused sobel + coefficients + 5 diffusion iters + bn_o/relu -> d_out[0:N)
    diffuse_fused<<<grid, 512, DIFF_SMEM_BYTES>>>(
        fptr, out, out + NTOT, bno_gamma, bno_beta, bno_mean, bno_var);
}

// round 10
// speedup vs baseline: 1.5795x; 1.0656x over previous
#include <cuda_runtime.h>
#include <cuda_bf16.h>
#include <cstdint>

// ===========================================================================
// Problem constants
// ===========================================================================
static constexpr int B  = 16;
static constexpr int H  = 128;
static constexpr int W  = 128;
static constexpr int C  = 64;
static constexpr int NTOT = B * H * W * C;    // 16,777,216
static constexpr float DT  = 0.2f;
static constexpr float EPS = 1e-3f;

// Scratch
__device__ float d_f_buf[NTOT];               // conv1 output (f == h_init)
// Pre-split bf16 weights: [conv][ty][plane(hi=0,lo=1)*12800 + n*200 + k]
__device__ __nv_bfloat16 d_wbf[2][3][2 * 64 * 200];

// ===========================================================================
// PTX helpers (plain-PTX, valid on .target sm_103)
// ===========================================================================
__device__ __forceinline__ uint32_t smem_u32(const void* p) {
    uint32_t a;
    asm("{ .reg .u64 t; cvta.to.shared.u64 t, %1; cvt.u32.u64 %0, t; }"
        : "=r"(a) : "l"(p));
    return a;
}

__device__ __forceinline__ void ldsm_x4(uint32_t (&r)[4], uint32_t addr) {
    asm volatile("ldmatrix.sync.aligned.m8n8.x4.shared.b16 {%0,%1,%2,%3}, [%4];"
                 : "=r"(r[0]), "=r"(r[1]), "=r"(r[2]), "=r"(r[3]) : "r"(addr));
}

__device__ __forceinline__ void mma_bf16(float (&d)[4], const uint32_t (&a)[4],
                                         uint32_t b0, uint32_t b1) {
    asm volatile(
        "mma.sync.aligned.m16n8k16.row.col.f32.bf16.bf16.f32 "
        "{%0,%1,%2,%3}, {%4,%5,%6,%7}, {%8,%9}, {%0,%1,%2,%3};"
        : "+f"(d[0]), "+f"(d[1]), "+f"(d[2]), "+f"(d[3])
        : "r"(a[0]), "r"(a[1]), "r"(a[2]), "r"(a[3]), "r"(b0), "r"(b1));
}

__device__ __forceinline__ void cp_async16(uint32_t saddr, const void* gaddr) {
    asm volatile("cp.async.cg.shared.global [%0], [%1], 16;"
                 :: "r"(saddr), "l"(gaddr) : "memory");
}
__device__ __forceinline__ void cp_commit() {
    asm volatile("cp.async.commit_group;" ::: "memory");
}
template <int N>
__device__ __forceinline__ void cp_wait() {
    asm volatile("cp.async.wait_group %0;" :: "n"(N) : "memory");
}

// ===========================================================================
// Weight prep: HWIO [3][3][64][64] -> per-ty [N=64][K=192] bf16 hi/lo split,
// rows padded to 200 bf16 (400 B).
// ===========================================================================
__global__ void prep_weights(const float* __restrict__ fw,
                             const float* __restrict__ gw)
{
    int idx = blockIdx.x * blockDim.x + threadIdx.x;     // 2*3*192*64 = 73728
    if (idx >= 73728) return;
    int conv = idx / 36864;  int r = idx - conv * 36864;
    int ty   = r / 12288;    r -= ty * 12288;
    int k    = r >> 6;       int n = r & 63;             // k 0..191, n = cout
    int tx   = k >> 6;       int ci = k & 63;
    const float* w = conv ? gw : fw;
    float v = w[(((ty * 3 + tx) * 64) + ci) * 64 + n];
    __nv_bfloat16 hi = __float2bfloat16_rn(v);
    __nv_bfloat16 lo = __float2bfloat16_rn(v - __bfloat162float(hi));
    __nv_bfloat16* base = &d_wbf[conv][ty][0];
    base[n * 200 + k]         = hi;
    base[12800 + n * 200 + k] = lo;
}

// ===========================================================================
// Conv v3: mma.sync bf16 3-pass, pipelined staging, 512 threads / 16 warps.
// Warp grid 4(m) x 4(n): warp tile m32 x n16. Same smem layout as v2.
// SMEM: A [2 planes][130*72] = 37,440 B ; B [3 ty][2 planes][64*200] = 153,600 B
// ===========================================================================
static constexpr int A_STRIDE = 72;
static constexpr int A_PLANE  = 130 * A_STRIDE;           // 9360 bf16
static constexpr int B_PLANE  = 64 * 200;                 // 12800 bf16
static constexpr int B_TY     = 2 * B_PLANE;              // 25600 bf16 per ty
static constexpr int CONV_SMEM_BYTES = (2 * A_PLANE + 3 * B_TY) * 2;  // 191,040
static constexpr int CT = 512;                            // conv threads

__global__ __launch_bounds__(CT, 1)
void conv_mma(const float* __restrict__ in,
              const __nv_bfloat16* __restrict__ wbase,    // d_wbf[conv]
              const float* __restrict__ gamma,
              const float* __restrict__ beta,
              const float* __restrict__ mean,
              const float* __restrict__ var,
              float* __restrict__ out)
{
    extern __shared__ __align__(16) char smem_raw[];
    __nv_bfloat16* s_ah = reinterpret_cast<__nv_bfloat16*>(smem_raw);
    __nv_bfloat16* s_al = s_ah + A_PLANE;
    __nv_bfloat16* s_b  = s_al + A_PLANE;                 // [3 ty][hi|lo]
    __shared__ float s_scale[64], s_shift[64];

    const int tid  = threadIdx.x;
    const int wid  = tid >> 5;
    const int lane = tid & 31;
    const int y    = blockIdx.x;
    const int b    = blockIdx.y;
    const int wm   = wid & 3;        // m32 tile: pixels wm*32..+31
    const int wn   = wid >> 2;       // n16 tile: couts  wn*16..+15

    if (tid < 64) {
        float sc = gamma[tid] * rsqrtf(var[tid] + EPS);
        s_scale[tid] = sc;
        s_shift[tid] = beta[tid] - mean[tid] * sc;
    }

    const uint32_t ah_base = smem_u32(s_ah);
    const uint32_t al_base = smem_u32(s_al);
    const uint32_t b_base  = smem_u32(s_b);

    // ---- issue cp.async for all 3 weight groups (one commit group per ty) ----
    {
#pragma unroll
        for (int tyg = 0; tyg < 3; ++tyg) {
            const char* src = reinterpret_cast<const char*>(wbase + tyg * B_TY);
            const uint32_t dst = b_base + (uint32_t)tyg * (B_TY * 2);
#pragma unroll
            for (int q = 0; q < 7; ++q) {
                int idx = tid + q * CT;
                if (idx < 3200) cp_async16(dst + idx * 16, src + idx * 16);
            }
            cp_commit();
        }
    }

    const float* inb = in + ((size_t)b * H) * W * C;

    const int r8  = lane & 7;
    const int sel = lane >> 3;
    const int a_row_off = (sel & 1) * 8 + r8;
    const int a_kh      = (sel >> 1) * 16;
    const int b_n_off   = (sel >> 1) * 8 + r8;
    const int b_kh      = (sel & 1) * 16;

    float4 pr[5];

    // ---- prefetch A row for ty=0 (input row y-1) ----
    {
        const int yy = y - 1;
        const bool rowok = (unsigned)yy < (unsigned)H;
#pragma unroll
        for (int q = 0; q < 5; ++q) {
            const int e = tid + q * CT;
            pr[q] = make_float4(0.f, 0.f, 0.f, 0.f);
            if (e < 2080) {
                const int px = e >> 4;
                const int c4 = (e & 15) << 2;
                if (rowok && px >= 1 && px <= 128)
                    pr[q] = *reinterpret_cast<const float4*>(
                        inb + ((size_t)yy * W + (px - 1)) * C + c4);
            }
        }
    }
    __syncthreads();   // s_scale/s_shift ready

    // ---- transform A(ty=0) -> smem buffer ----
    {
        const int yy = y - 1;
        const bool rowok = (unsigned)yy < (unsigned)H;
#pragma unroll
        for (int q = 0; q < 5; ++q) {
            const int e = tid + q * CT;
            if (e >= 2080) break;
            const int px = e >> 4;
            const int c4 = (e & 15) << 2;
            float v0 = 0.f, v1 = 0.f, v2 = 0.f, v3 = 0.f;
            if (rowok && px >= 1 && px <= 128) {
                v0 = fmaxf(fmaf(pr[q].x, s_scale[c4],     s_shift[c4]),     0.f);
                v1 = fmaxf(fmaf(pr[q].y, s_scale[c4 + 1], s_shift[c4 + 1]), 0.f);
                v2 = fmaxf(fmaf(pr[q].z, s_scale[c4 + 2], s_shift[c4 + 2]), 0.f);
                v3 = fmaxf(fmaf(pr[q].w, s_scale[c4 + 3], s_shift[c4 + 3]), 0.f);
            }
            __nv_bfloat162 h01 = __floats2bfloat162_rn(v0, v1);
            __nv_bfloat162 h23 = __floats2bfloat162_rn(v2, v3);
            __nv_bfloat162 l01 = __floats2bfloat162_rn(
                v0 - __bfloat162float(h01.x), v1 - __bfloat162float(h01.y));
            __nv_bfloat162 l23 = __floats2bfloat162_rn(
                v2 - __bfloat162float(h23.x), v3 - __bfloat162float(h23.y));
            const int o = px * A_STRIDE + c4;
            *reinterpret_cast<__nv_bfloat162*>(s_ah + o)     = h01;
            *reinterpret_cast<__nv_bfloat162*>(s_ah + o + 2) = h23;
            *reinterpret_cast<__nv_bfloat162*>(s_al + o)     = l01;
            *reinterpret_cast<__nv_bfloat162*>(s_al + o + 2) = l23;
        }
    }
    cp_wait<2>();      // B[0] arrived
    __syncthreads();

    float acc[2][2][4];            // [m16 half][n8 half]
#pragma unroll
    for (int mt = 0; mt < 2; ++mt)
#pragma unroll
        for (int nt = 0; nt < 2; ++nt)
#pragma unroll
            for (int e = 0; e < 4; ++e) acc[mt][nt][e] = 0.f;

#pragma unroll
    for (int ty = 0; ty < 3; ++ty) {
        // ---- prefetch A row for ty+1 (input row y+ty) into registers ----
        if (ty < 2) {
            const int yy = y + ty;
            const bool rowok = (unsigned)yy < (unsigned)H;
#pragma unroll
            for (int q = 0; q < 5; ++q) {
                const int e = tid + q * CT;
                pr[q] = make_float4(0.f, 0.f, 0.f, 0.f);
                if (e < 2080) {
                    const int px = e >> 4;
                    const int c4 = (e & 15) << 2;
                    if (rowok && px >= 1 && px <= 128)
                        pr[q] = *reinterpret_cast<const float4*>(
                            inb + ((size_t)yy * W + (px - 1)) * C + c4);
                }
            }
        }

        // ---- mma over this ty's 12 k-steps ----
        const uint32_t bh_base = b_base + (uint32_t)ty * (B_TY * 2);
        const uint32_t bl_base = bh_base + B_PLANE * 2;
#pragma unroll
        for (int ks = 0; ks < 12; ++ks) {
            const int tx   = ks >> 2;
            const int ci16 = ks & 3;

            uint32_t afr[2][2][4];     // [m16 half][plane]
#pragma unroll
            for (int mt = 0; mt < 2; ++mt) {
                const int px = wm * 32 + mt * 16 + a_row_off + tx;
                const uint32_t off = (uint32_t)(px * (A_STRIDE * 2) + ci16 * 32 + a_kh);
                ldsm_x4(afr[mt][0], ah_base + off);
                ldsm_x4(afr[mt][1], al_base + off);
            }
            uint32_t bfr[2][4];        // [plane]: n16 x k16 for this warp
            {
                const int n = wn * 16 + b_n_off;
                const uint32_t off = (uint32_t)(n * 400 + tx * 128 + ci16 * 32 + b_kh);
                ldsm_x4(bfr[0], bh_base + off);
                ldsm_x4(bfr[1], bl_base + off);
            }
#pragma unroll
            for (int mt = 0; mt < 2; ++mt)
#pragma unroll
                for (int nt = 0; nt < 2; ++nt) {
                    const int h2 = nt * 2;
                    mma_bf16(acc[mt][nt], afr[mt][0], bfr[0][h2], bfr[0][h2 + 1]);
                    mma_bf16(acc[mt][nt], afr[mt][0], bfr[1][h2], bfr[1][h2 + 1]);
                    mma_bf16(acc[mt][nt], afr[mt][1], bfr[0][h2], bfr[0][h2 + 1]);
                }
        }

        // ---- transform prefetched regs into the A buffer for next ty ----
        if (ty < 2) {
            __syncthreads();          // everyone done reading A(ty)
            const int yy = y + ty;
            const bool rowok = (unsigned)yy < (unsigned)H;
#pragma unroll
            for (int q = 0; q < 5; ++q) {
                const int e = tid + q * CT;
                if (e >= 2080) break;
                const int px = e >> 4;
                const int c4 = (e & 15) << 2;
                float v0 = 0.f, v1 = 0.f, v2 = 0.f, v3 = 0.f;
                if (rowok && px >= 1 && px <= 128) {
                    v0 = fmaxf(fmaf(pr[q].x, s_scale[c4],     s_shift[c4]),     0.f);
                    v1 = fmaxf(fmaf(pr[q].y, s_scale[c4 + 1], s_shift[c4 + 1]), 0.f);
                    v2 = fmaxf(fmaf(pr[q].z, s_scale[c4 + 2], s_shift[c4 + 2]), 0.f);
                    v3 = fmaxf(fmaf(pr[q].w, s_scale[c4 + 3], s_shift[c4 + 3]), 0.f);
                }
                __nv_bfloat162 h01 = __floats2bfloat162_rn(v0, v1);
                __nv_bfloat162 h23 = __floats2bfloat162_rn(v2, v3);
                __nv_bfloat162 l01 = __floats2bfloat162_rn(
                    v0 - __bfloat162float(h01.x), v1 - __bfloat162float(h01.y));
                __nv_bfloat162 l23 = __floats2bfloat162_rn(
                    v2 - __bfloat162float(h23.x), v3 - __bfloat162float(h23.y));
                const int o = px * A_STRIDE + c4;
                *reinterpret_cast<__nv_bfloat162*>(s_ah + o)     = h01;
                *reinterpret_cast<__nv_bfloat162*>(s_ah + o + 2) = h23;
                *reinterpret_cast<__nv_bfloat162*>(s_al + o)     = l01;
                *reinterpret_cast<__nv_bfloat162*>(s_al + o + 2) = l23;
            }
            if (ty == 0) cp_wait<1>();   // B[1] arrived
            else         cp_wait<0>();   // B[2] arrived
            __syncthreads();
        }
    }

    // ---- epilogue: fp32 accumulators -> NHWC output ----
    float* ob = out + (((size_t)b * H + y) * W) * C;
#pragma unroll
    for (int mt = 0; mt < 2; ++mt) {
        const int x0 = wm * 32 + mt * 16 + (lane >> 2);
        float* row0 = ob + (size_t)x0 * C;
        float* row1 = row0 + 8 * C;
#pragma unroll
        for (int nt = 0; nt < 2; ++nt) {
            const int co = wn * 16 + nt * 8 + (lane & 3) * 2;
            *reinterpret_cast<float2*>(row0 + co) = make_float2(acc[mt][nt][0], acc[mt][nt][1]);
            *reinterpret_cast<float2*>(row1 + co) = make_float2(acc[mt][nt][2], acc[mt][nt][3]);
        }
    }
}

// ===========================================================================
// Fused diffusion (R8/R9 version): channel-pair mapping, coefficients in regs.
// ===========================================================================
static constexpr int DIFF_SMEM_BYTES = 4 * 8192 * 4;   // 131,072 B

__global__ __launch_bounds__(512, 1)
void diffuse_fused(const float* __restrict__ f,
                   float* __restrict__ outh,
                   const float* __restrict__ g,
                   const float* __restrict__ gamma,
                   const float* __restrict__ beta,
                   const float* __restrict__ mean,
                   const float* __restrict__ var)
{
    extern __shared__ float sm[];
    float* P0 = sm;              // F, then h ping
    float* P1 = sm + 8192;       // G, then h pong
    float* BX = sm + 16384;      // 2*DT*Dx
    float* BY = sm + 24576;      // 2*DT*Dy
    __shared__ float sc[64], sh[64];

    const int tid = threadIdx.x;
    const int y   = blockIdx.x;
    const int b   = blockIdx.y;

    if (tid < 64) {
        float s = gamma[tid] * rsqrtf(var[tid] + EPS);
        sc[tid] = s;
        sh[tid] = beta[tid] - mean[tid] * s;
    }

    const size_t rowbase = (((size_t)b * H) + y) * W * C;
    const float* frow = f + rowbase;
    const float* grow = g + rowbase;
#pragma unroll
    for (int q = 0; q < 4; ++q) {
        const int idx = (tid + q * 512) * 4;
        *reinterpret_cast<float4*>(P0 + idx) = *reinterpret_cast<const float4*>(frow + idx);
        *reinterpret_cast<float4*>(P1 + idx) = *reinterpret_cast<const float4*>(grow + idx);
    }
    __syncthreads();

    const int c = (tid & 31) * 2;
    const float2 sc2 = make_float2(sc[c], sc[c + 1]);
    const float2 sh2 = make_float2(sh[c], sh[c + 1]);

    const int ym = (y == 0) ? 1 : y - 1;
    const int yp = (y == H - 1) ? H - 2 : y + 1;
    const float* fm = f + ((((size_t)b * H) + ym) * W) * C;
    const float* fp = f + ((((size_t)b * H) + yp) * W) * C;

    float2 hprev[8], hcur[8], E2r[8], axr[8], cdr[8], cfr[8];

#pragma unroll
    for (int j = 0; j < 8; ++j) {
        const int i = (tid + j * 512) * 2;
        const int x = i >> 6;
        const int xm = (x == 0) ? 1 : x - 1;
        const int xp = (x == W - 1) ? W - 2 : x + 1;

        const float2 f2 = *reinterpret_cast<const float2*>(P0 + i);
        const float2 g2 = *reinterpret_cast<const float2*>(P1 + i);

        const float2 am = *reinterpret_cast<const float2*>(fm + xm * 64 + c);
        const float2 a0 = *reinterpret_cast<const float2*>(fm + x  * 64 + c);
        const float2 ap = *reinterpret_cast<const float2*>(fm + xp * 64 + c);
        const float2 bm = *reinterpret_cast<const float2*>(fp + xm * 64 + c);
        const float2 b0 = *reinterpret_cast<const float2*>(fp + x  * 64 + c);
        const float2 bp = *reinterpret_cast<const float2*>(fp + xp * 64 + c);
        const float2 fxm = *reinterpret_cast<const float2*>(P0 + xm * 64 + c);
        const float2 fxp = *reinterpret_cast<const float2*>(P0 + xp * 64 + c);

        float dyx = (bm.x + 2.f * b0.x + bp.x) - (am.x + 2.f * a0.x + ap.x);
        float dyy = (bm.y + 2.f * b0.y + bp.y) - (am.y + 2.f * a0.y + ap.y);
        float dxx = (ap.x - am.x) + 2.f * (fxp.x - fxm.x) + (bp.x - bm.x);
        float dxy = (ap.y - am.y) + 2.f * (fxp.y - fxm.y) + (bp.y - bm.y);

        float bxx = (2.f * DT) / (0.25f * dyx * dyx + 1.f);
        float bxy = (2.f * DT) / (0.25f * dyy * dyy + 1.f);
        float byx = (2.f * DT) / (0.25f * dxx * dxx + 1.f);
        float byy = (2.f * DT) / (0.25f * dxy * dxy + 1.f);
        *reinterpret_cast<float2*>(BX + i) = make_float2(bxx, bxy);
        *reinterpret_cast<float2*>(BY + i) = make_float2(byx, byy);

        cdr[j] = make_float2(1.f / (1.f + bxx + byx), 1.f / (1.f + bxy + byy));
        axr[j] = make_float2(DT * g2.x, DT * g2.y);
        cfr[j] = make_float2(2.f * DT * f2.x, 2.f * DT * f2.y);
        hprev[j] = f2;
        hcur[j]  = f2;

        const int ixm = (i + 8192 - 64) & 8191;
        const int ixp = (i + 64) & 8191;
        const float2 gxm = *reinterpret_cast<const float2*>(P1 + ixm);
        const float2 gxp = *reinterpret_cast<const float2*>(P1 + ixp);
        const float gcm = P1[(i & ~63) | ((c + 63) & 63)];
        const float gcp = P1[(i & ~63) | ((c + 2) & 63)];
        E2r[j].x = DT * ((gxm.x - gxp.x) + (gcm - g2.y));
        E2r[j].y = DT * ((gxm.y - gxp.y) + (g2.x - gcp));
    }
    __syncthreads();

#pragma unroll
    for (int k = 0; k < 5; ++k) {
        float* rb = (k & 1) ? P1 : P0;
        float* wb = (k & 1) ? P0 : P1;
#pragma unroll
        for (int j = 0; j < 8; ++j) {
            const int i = (tid + j * 512) * 2;
            const int ixm = (i + 8192 - 64) & 8191;
            const int ixp = (i + 64) & 8191;
            const float2 bx2 = *reinterpret_cast<const float2*>(BX + i);
            const float2 by2 = *reinterpret_cast<const float2*>(BY + i);
            const float2 rxm = *reinterpret_cast<const float2*>(rb + ixm);
            const float2 rxp = *reinterpret_cast<const float2*>(rb + ixp);
            const float rcm = rb[(i & ~63) | ((c + 63) & 63)];
            const float rcp = rb[(i & ~63) | ((c + 2) & 63)];
            const float2 hc = hcur[j];
            const float2 ax = axr[j];

            float s0 = (1.f - bx2.x - by2.x) * hprev[j].x;
            s0 = fmaf(-E2r[j].x, hc.x, s0);
            s0 = fmaf(bx2.x, rxm.x + rxp.x, s0);
            s0 = fmaf(ax.x,  rxp.x - rxm.x, s0);
            s0 = fmaf(by2.x, rcm + hc.y, s0);
            s0 = fmaf(ax.x,  hc.y - rcm, s0);
            s0 = (s0 + cfr[j].x) * cdr[j].x;

            float s1 = (1.f - bx2.y - by2.y) * hprev[j].y;
            s1 = fmaf(-E2r[j].y, hc.y, s1);
            s1 = fmaf(bx2.y, rxm.y + rxp.y, s1);
            s1 = fmaf(ax.y,  rxp.y - rxm.y, s1);
            s1 = fmaf(by2.y, hc.x + rcp, s1);
            s1 = fmaf(ax.y,  rcp - hc.x, s1);
            s1 = (s1 + cfr[j].y) * cdr[j].y;

            hprev[j] = hc;
            hcur[j]  = make_float2(s0, s1);
            if (k < 4) *reinterpret_cast<float2*>(wb + i) = hcur[j];
        }
        if (k < 4) __syncthreads();
    }

    float* o = outh + rowbase;
#pragma unroll
    for (int j = 0; j < 8; ++j) {
        const int i = (tid + j * 512) * 2;
        float2 r = make_float2(fmaxf(fmaf(hcur[j].x, sc2.x, sh2.x), 0.f),
                               fmaxf(fmaf(hcur[j].y, sc2.y, sh2.y), 0.f));
        *reinterpret_cast<float2*>(o + i) = r;
    }
}

// ===========================================================================
extern "C" void kernel_launch(void* const* d_in, const int* in_sizes, int n_in,
                              void* d_out, int out_size)
{
    const float* x   = (const float*)d_in[0];
    const float* f_w = (const float*)d_in[1];
    const float* g_w = (const float*)d_in[2];
    const float* bnf_gamma = (const float*)d_in[3];
    const float* bnf_beta  = (const float*)d_in[4];
    const float* bnf_mean  = (const float*)d_in[5];
    const float* bnf_var   = (const float*)d_in[6];
    const float* bng_gamma = (const float*)d_in[7];
    const float* bng_beta  = (const float*)d_in[8];
    const float* bng_mean  = (const float*)d_in[9];
    const float* bng_var   = (const float*)d_in[10];
    const float* bno_gamma = (const float*)d_in[11];
    const float* bno_beta  = (const float*)d_in[12];
    const float* bno_mean  = (const float*)d_in[13];
    const float* bno_var   = (const float*)d_in[14];

    float* out = (float*)d_out;            // [0:N) = h, [N:2N) = g

    float* fptr = nullptr;
    cudaGetSymbolAddress((void**)&fptr, d_f_buf);
    __nv_bfloat16* wptr = nullptr;
    cudaGetSymbolAddress((void**)&wptr, d_wbf);

    cudaFuncSetAttribute(conv_mma,
                         cudaFuncAttributeMaxDynamicSharedMemorySize, CONV_SMEM_BYTES);
    cudaFuncSetAttribute(diffuse_fused,
                         cudaFuncAttributeMaxDynamicSharedMemorySize, DIFF_SMEM_BYTES);

    // 1) weight transform (both convs)
    prep_weights<<<288, 256>>>(f_w, g_w);

    dim3 grid(H, B);

    // 2) f = conv(relu(bn_f(x)), f_w)
    conv_mma<<<grid, CT, CONV_SMEM_BYTES>>>(
        x, wptr, bnf_gamma, bnf_beta, bnf_mean, bnf_var, fptr);

    // 3) g = conv(relu(bn_g(f)), g_w) -> d_out[N:2N)
    conv_mma<<<grid, CT, CONV_SMEM_BYTES>>>(
        fptr, wptr + 3 * B_TY, bng_gamma, bng_beta, bng_mean, bng_var, out + NTOT);

    // 4) fused sobel + coefficients + 5 diffusion iters + bn_o/relu -> d_out[0:N)
    diffuse_fused<<<grid, 512, DIFF_SMEM_BYTES>>>(
        fptr, out, out + NTOT, bno_gamma, bno_beta, bno_mean, bno_var);
}

// round 11
// speedup vs baseline: 1.8156x; 1.1495x over previous
#include <cuda_runtime.h>
#include <cuda_bf16.h>
#include <cstdint>

// ===========================================================================
// Problem constants
// ===========================================================================
static constexpr int B  = 16;
static constexpr int H  = 128;
static constexpr int W  = 128;
static constexpr int C  = 64;
static constexpr int NTOT = B * H * W * C;    // 16,777,216
static constexpr float DT  = 0.2f;
static constexpr float EPS = 1e-3f;

// Scratch
__device__ float d_f_buf[NTOT];               // conv1 output (f == h_init)
// Pre-split bf16 weights: [conv][ty][plane(hi=0,lo=1)*12800 + n*200 + k]
__device__ __nv_bfloat16 d_wbf[2][3][2 * 64 * 200];

// ===========================================================================
// PTX helpers (plain-PTX, valid on .target sm_103)
// ===========================================================================
__device__ __forceinline__ uint32_t smem_u32(const void* p) {
    uint32_t a;
    asm("{ .reg .u64 t; cvta.to.shared.u64 t, %1; cvt.u32.u64 %0, t; }"
        : "=r"(a) : "l"(p));
    return a;
}

__device__ __forceinline__ void ldsm_x4(uint32_t (&r)[4], uint32_t addr) {
    asm volatile("ldmatrix.sync.aligned.m8n8.x4.shared.b16 {%0,%1,%2,%3}, [%4];"
                 : "=r"(r[0]), "=r"(r[1]), "=r"(r[2]), "=r"(r[3]) : "r"(addr));
}

__device__ __forceinline__ void mma_bf16(float (&d)[4], const uint32_t (&a)[4],
                                         uint32_t b0, uint32_t b1) {
    asm volatile(
        "mma.sync.aligned.m16n8k16.row.col.f32.bf16.bf16.f32 "
        "{%0,%1,%2,%3}, {%4,%5,%6,%7}, {%8,%9}, {%0,%1,%2,%3};"
        : "+f"(d[0]), "+f"(d[1]), "+f"(d[2]), "+f"(d[3])
        : "r"(a[0]), "r"(a[1]), "r"(a[2]), "r"(a[3]), "r"(b0), "r"(b1));
}

__device__ __forceinline__ void cp_async16(uint32_t saddr, const void* gaddr) {
    asm volatile("cp.async.cg.shared.global [%0], [%1], 16;"
                 :: "r"(saddr), "l"(gaddr) : "memory");
}
__device__ __forceinline__ void cp_commit() {
    asm volatile("cp.async.commit_group;" ::: "memory");
}
template <int N>
__device__ __forceinline__ void cp_wait() {
    asm volatile("cp.async.wait_group %0;" :: "n"(N) : "memory");
}

// ===========================================================================
// Weight prep: HWIO [3][3][64][64] -> per-ty [N=64][K=192] bf16 hi/lo split,
// rows padded to 200 bf16 (400 B).
// ===========================================================================
__global__ void prep_weights(const float* __restrict__ fw,
                             const float* __restrict__ gw)
{
    int idx = blockIdx.x * blockDim.x + threadIdx.x;     // 2*3*192*64 = 73728
    if (idx >= 73728) return;
    int conv = idx / 36864;  int r = idx - conv * 36864;
    int ty   = r / 12288;    r -= ty * 12288;
    int k    = r >> 6;       int n = r & 63;             // k 0..191, n = cout
    int tx   = k >> 6;       int ci = k & 63;
    const float* w = conv ? gw : fw;
    float v = w[(((ty * 3 + tx) * 64) + ci) * 64 + n];
    __nv_bfloat16 hi = __float2bfloat16_rn(v);
    __nv_bfloat16 lo = __float2bfloat16_rn(v - __bfloat162float(hi));
    __nv_bfloat16* base = &d_wbf[conv][ty][0];
    base[n * 200 + k]         = hi;
    base[12800 + n * 200 + k] = lo;
}

// ===========================================================================
// Conv v4: 2 output rows per block (M=256), mma.sync bf16 3-pass.
// Grid (64, 16); 512 threads / 16 warps as 8(m) x 2(n): warp tile m32 x n32.
// A: input rows y0-1..y0+2 in 3 rotating slots (slot = row % 3; row 3
//    overwrites slot 0 after ty=0 which only reads slots 0,1).
// B: 2 cp.async-double-buffered ty planes (B0,B1 upfront, B2 after ty0).
// SMEM: 3 * 18720 + 2 * 25600 bf16 = 214,720 B -> 1 CTA/SM.
// ===========================================================================
static constexpr int A_STRIDE = 72;
static constexpr int A_PLANE  = 130 * A_STRIDE;           // 9360 bf16
static constexpr int A_SLOT   = 2 * A_PLANE;              // hi+lo, 18720 bf16
static constexpr int B_PLANE  = 64 * 200;                 // 12800 bf16
static constexpr int B_TY     = 2 * B_PLANE;              // 25600 bf16 per ty
static constexpr int CONV_SMEM_BYTES = (3 * A_SLOT + 2 * B_TY) * 2;  // 214,720
static constexpr int CT = 512;

__global__ __launch_bounds__(CT, 1)
void conv_mma(const float* __restrict__ in,
              const __nv_bfloat16* __restrict__ wbase,    // d_wbf[conv]
              const float* __restrict__ gamma,
              const float* __restrict__ beta,
              const float* __restrict__ mean,
              const float* __restrict__ var,
              float* __restrict__ out)
{
    extern __shared__ __align__(16) char smem_raw[];
    __nv_bfloat16* s_a = reinterpret_cast<__nv_bfloat16*>(smem_raw);   // 3 slots
    __nv_bfloat16* s_b = s_a + 3 * A_SLOT;                             // 2 bufs
    __shared__ float s_scale[64], s_shift[64];

    const int tid  = threadIdx.x;
    const int wid  = tid >> 5;
    const int lane = tid & 31;
    const int y0   = blockIdx.x * 2;
    const int b    = blockIdx.y;
    const int wm   = wid & 7;        // m32 tile over 256 px
    const int wn   = wid >> 3;       // n32 tile over 64 couts
    const int r_out = wm >> 2;       // output row within block (0/1)
    const int xw    = (wm & 3) * 32; // x offset of warp tile

    if (tid < 64) {
        float sc = gamma[tid] * rsqrtf(var[tid] + EPS);
        s_scale[tid] = sc;
        s_shift[tid] = beta[tid] - mean[tid] * sc;
    }

    const uint32_t a_base0 = smem_u32(s_a);
    const uint32_t b_base  = smem_u32(s_b);

    // ---- issue cp.async for B ty=0 (buf0, group0) and ty=1 (buf1, group1) ----
#pragma unroll
    for (int tyg = 0; tyg < 2; ++tyg) {
        const char* src = reinterpret_cast<const char*>(wbase + tyg * B_TY);
        const uint32_t dst = b_base + (uint32_t)tyg * (B_TY * 2);
#pragma unroll
        for (int q = 0; q < 7; ++q) {
            int idx = tid + q * CT;
            if (idx < 3200) cp_async16(dst + idx * 16, src + idx * 16);
        }
        cp_commit();
    }

    const float* inb = in + ((size_t)b * H) * W * C;

    const int r8  = lane & 7;
    const int sel = lane >> 3;
    const int a_row_off = (sel & 1) * 8 + r8;
    const int a_kh      = (sel >> 1) * 16;
    const int b_n_off   = (sel >> 1) * 8 + r8;
    const int b_kh      = (sel & 1) * 16;

    // ---- prefetch input row y0+2 (4th row) into registers ----
    float4 pr[5];
    {
        const int yy = y0 + 2;
        const bool rowok = (unsigned)yy < (unsigned)H;
#pragma unroll
        for (int q = 0; q < 5; ++q) {
            const int e = tid + q * CT;
            pr[q] = make_float4(0.f, 0.f, 0.f, 0.f);
            if (e < 2080) {
                const int px = e >> 4;
                const int c4 = (e & 15) << 2;
                if (rowok && px >= 1 && px <= 128)
                    pr[q] = *reinterpret_cast<const float4*>(
                        inb + ((size_t)yy * W + (px - 1)) * C + c4);
            }
        }
    }
    __syncthreads();   // s_scale/s_shift ready

    // ---- stage input rows y0-1, y0, y0+1 into slots 0,1,2 ----
#pragma unroll
    for (int q = 0; q < 13; ++q) {
        const int idx = tid + q * CT;
        if (idx >= 6240) break;
        const int r  = idx / 2080;
        const int e  = idx - r * 2080;
        const int px = e >> 4;
        const int c4 = (e & 15) << 2;
        const int yy = y0 - 1 + r;
        float v0 = 0.f, v1 = 0.f, v2 = 0.f, v3 = 0.f;
        if ((unsigned)yy < (unsigned)H && px >= 1 && px <= 128) {
            float4 t = *reinterpret_cast<const float4*>(
                inb + ((size_t)yy * W + (px - 1)) * C + c4);
            v0 = fmaxf(fmaf(t.x, s_scale[c4],     s_shift[c4]),     0.f);
            v1 = fmaxf(fmaf(t.y, s_scale[c4 + 1], s_shift[c4 + 1]), 0.f);
            v2 = fmaxf(fmaf(t.z, s_scale[c4 + 2], s_shift[c4 + 2]), 0.f);
            v3 = fmaxf(fmaf(t.w, s_scale[c4 + 3], s_shift[c4 + 3]), 0.f);
        }
        __nv_bfloat162 h01 = __floats2bfloat162_rn(v0, v1);
        __nv_bfloat162 h23 = __floats2bfloat162_rn(v2, v3);
        __nv_bfloat162 l01 = __floats2bfloat162_rn(
            v0 - __bfloat162float(h01.x), v1 - __bfloat162float(h01.y));
        __nv_bfloat162 l23 = __floats2bfloat162_rn(
            v2 - __bfloat162float(h23.x), v3 - __bfloat162float(h23.y));
        __nv_bfloat16* slot = s_a + r * A_SLOT;
        const int o = px * A_STRIDE + c4;
        *reinterpret_cast<__nv_bfloat162*>(slot + o)              = h01;
        *reinterpret_cast<__nv_bfloat162*>(slot + o + 2)          = h23;
        *reinterpret_cast<__nv_bfloat162*>(slot + A_PLANE + o)     = l01;
        *reinterpret_cast<__nv_bfloat162*>(slot + A_PLANE + o + 2) = l23;
    }
    cp_wait<0>();      // B0, B1 arrived
    __syncthreads();

    float acc[2][4][4];            // [m16 half][n8 quarter]
#pragma unroll
    for (int mt = 0; mt < 2; ++mt)
#pragma unroll
        for (int nt = 0; nt < 4; ++nt)
#pragma unroll
            for (int e = 0; e < 4; ++e) acc[mt][nt][e] = 0.f;

    // ---------------- mma over 3 ty ----------------
#pragma unroll
    for (int ty = 0; ty < 3; ++ty) {
        int slot = r_out + ty;           // input row index
        if (slot >= 3) slot -= 3;        // rotating slot
        const uint32_t ah_base = a_base0 + (uint32_t)slot * (A_SLOT * 2);
        const uint32_t al_base = ah_base + A_PLANE * 2;
        const int bbuf = (ty == 1) ? 1 : 0;          // ty0->buf0, ty1->buf1, ty2->buf0
        const uint32_t bh_base = b_base + (uint32_t)bbuf * (B_TY * 2);
        const uint32_t bl_base = bh_base + B_PLANE * 2;

#pragma unroll
        for (int ks = 0; ks < 12; ++ks) {
            const int tx   = ks >> 2;
            const int ci16 = ks & 3;

            uint32_t afr[2][2][4];     // [m16 half][plane]
#pragma unroll
            for (int mt = 0; mt < 2; ++mt) {
                const int px = xw + mt * 16 + a_row_off + tx;
                const uint32_t off = (uint32_t)(px * (A_STRIDE * 2) + ci16 * 32 + a_kh);
                ldsm_x4(afr[mt][0], ah_base + off);
                ldsm_x4(afr[mt][1], al_base + off);
            }
            uint32_t bfr[2][2][4];     // [n16 group][plane]
#pragma unroll
            for (int g = 0; g < 2; ++g) {
                const int n = wn * 32 + g * 16 + b_n_off;
                const uint32_t off = (uint32_t)(n * 400 + tx * 128 + ci16 * 32 + b_kh);
                ldsm_x4(bfr[g][0], bh_base + off);
                ldsm_x4(bfr[g][1], bl_base + off);
            }
#pragma unroll
            for (int mt = 0; mt < 2; ++mt)
#pragma unroll
                for (int nt = 0; nt < 4; ++nt) {
                    const int g = nt >> 1, h2 = (nt & 1) * 2;
                    mma_bf16(acc[mt][nt], afr[mt][0], bfr[g][0][h2], bfr[g][0][h2 + 1]);
                    mma_bf16(acc[mt][nt], afr[mt][0], bfr[g][1][h2], bfr[g][1][h2 + 1]);
                    mma_bf16(acc[mt][nt], afr[mt][1], bfr[g][0][h2], bfr[g][0][h2 + 1]);
                }
        }

        if (ty == 0) {
            // slot0 (row y0-1) dead; B buf0 dead. Refill both for ty=2.
            __syncthreads();
            // transform prefetched row y0+2 into slot 0
            const int yy = y0 + 2;
            const bool rowok = (unsigned)yy < (unsigned)H;
#pragma unroll
            for (int q = 0; q < 5; ++q) {
                const int e = tid + q * CT;
                if (e >= 2080) break;
                const int px = e >> 4;
                const int c4 = (e & 15) << 2;
                float v0 = 0.f, v1 = 0.f, v2 = 0.f, v3 = 0.f;
                if (rowok && px >= 1 && px <= 128) {
                    v0 = fmaxf(fmaf(pr[q].x, s_scale[c4],     s_shift[c4]),     0.f);
                    v1 = fmaxf(fmaf(pr[q].y, s_scale[c4 + 1], s_shift[c4 + 1]), 0.f);
                    v2 = fmaxf(fmaf(pr[q].z, s_scale[c4 + 2], s_shift[c4 + 2]), 0.f);
                    v3 = fmaxf(fmaf(pr[q].w, s_scale[c4 + 3], s_shift[c4 + 3]), 0.f);
                }
                __nv_bfloat162 h01 = __floats2bfloat162_rn(v0, v1);
                __nv_bfloat162 h23 = __floats2bfloat162_rn(v2, v3);
                __nv_bfloat162 l01 = __floats2bfloat162_rn(
                    v0 - __bfloat162float(h01.x), v1 - __bfloat162float(h01.y));
                __nv_bfloat162 l23 = __floats2bfloat162_rn(
                    v2 - __bfloat162float(h23.x), v3 - __bfloat162float(h23.y));
                __nv_bfloat16* slot0 = s_a;
                const int o = px * A_STRIDE + c4;
                *reinterpret_cast<__nv_bfloat162*>(slot0 + o)              = h01;
                *reinterpret_cast<__nv_bfloat162*>(slot0 + o + 2)          = h23;
                *reinterpret_cast<__nv_bfloat162*>(slot0 + A_PLANE + o)     = l01;
                *reinterpret_cast<__nv_bfloat162*>(slot0 + A_PLANE + o + 2) = l23;
            }
            // B ty=2 into buf0 (group2)
            {
                const char* src = reinterpret_cast<const char*>(wbase + 2 * B_TY);
                const uint32_t dst = b_base;
#pragma unroll
                for (int q = 0; q < 7; ++q) {
                    int idx = tid + q * CT;
                    if (idx < 3200) cp_async16(dst + idx * 16, src + idx * 16);
                }
                cp_commit();
            }
            // ty=1 uses slot1/slot2 + buf1: all ready; no barrier needed here.
        } else if (ty == 1) {
            cp_wait<0>();      // B2 arrived
            __syncthreads();   // slot0 rewrite + B2 visible to all
        }
    }

    // ---- epilogue: fp32 accumulators -> NHWC output ----
    const int ygl = y0 + r_out;
    float* ob = out + (((size_t)b * H + ygl) * W) * C;
#pragma unroll
    for (int mt = 0; mt < 2; ++mt) {
        const int x0 = xw + mt * 16 + (lane >> 2);
        float* row0 = ob + (size_t)x0 * C;
        float* row1 = row0 + 8 * C;
#pragma unroll
        for (int nt = 0; nt < 4; ++nt) {
            const int co = wn * 32 + nt * 8 + (lane & 3) * 2;
            *reinterpret_cast<float2*>(row0 + co) = make_float2(acc[mt][nt][0], acc[mt][nt][1]);
            *reinterpret_cast<float2*>(row1 + co) = make_float2(acc[mt][nt][2], acc[mt][nt][3]);
        }
    }
}

// ===========================================================================
// Fused diffusion (R8-R10 version): channel-pair mapping, coefficients in regs.
// ===========================================================================
static constexpr int DIFF_SMEM_BYTES = 4 * 8192 * 4;   // 131,072 B

__global__ __launch_bounds__(512, 1)
void diffuse_fused(const float* __restrict__ f,
                   float* __restrict__ outh,
                   const float* __restrict__ g,
                   const float* __restrict__ gamma,
                   const float* __restrict__ beta,
                   const float* __restrict__ mean,
                   const float* __restrict__ var)
{
    extern __shared__ float sm[];
    float* P0 = sm;              // F, then h ping
    float* P1 = sm + 8192;       // G, then h pong
    float* BX = sm + 16384;      // 2*DT*Dx
    float* BY = sm + 24576;      // 2*DT*Dy
    __shared__ float sc[64], sh[64];

    const int tid = threadIdx.x;
    const int y   = blockIdx.x;
    const int b   = blockIdx.y;

    if (tid < 64) {
        float s = gamma[tid] * rsqrtf(var[tid] + EPS);
        sc[tid] = s;
        sh[tid] = beta[tid] - mean[tid] * s;
    }

    const size_t rowbase = (((size_t)b * H) + y) * W * C;
    const float* frow = f + rowbase;
    const float* grow = g + rowbase;
#pragma unroll
    for (int q = 0; q < 4; ++q) {
        const int idx = (tid + q * 512) * 4;
        *reinterpret_cast<float4*>(P0 + idx) = *reinterpret_cast<const float4*>(frow + idx);
        *reinterpret_cast<float4*>(P1 + idx) = *reinterpret_cast<const float4*>(grow + idx);
    }
    __syncthreads();

    const int c = (tid & 31) * 2;
    const float2 sc2 = make_float2(sc[c], sc[c + 1]);
    const float2 sh2 = make_float2(sh[c], sh[c + 1]);

    const int ym = (y == 0) ? 1 : y - 1;
    const int yp = (y == H - 1) ? H - 2 : y + 1;
    const float* fm = f + ((((size_t)b * H) + ym) * W) * C;
    const float* fp = f + ((((size_t)b * H) + yp) * W) * C;

    float2 hprev[8], hcur[8], E2r[8], axr[8], cdr[8], cfr[8];

#pragma unroll
    for (int j = 0; j < 8; ++j) {
        const int i = (tid + j * 512) * 2;
        const int x = i >> 6;
        const int xm = (x == 0) ? 1 : x - 1;
        const int xp = (x == W - 1) ? W - 2 : x + 1;

        const float2 f2 = *reinterpret_cast<const float2*>(P0 + i);
        const float2 g2 = *reinterpret_cast<const float2*>(P1 + i);

        const float2 am = *reinterpret_cast<const float2*>(fm + xm * 64 + c);
        const float2 a0 = *reinterpret_cast<const float2*>(fm + x  * 64 + c);
        const float2 ap = *reinterpret_cast<const float2*>(fm + xp * 64 + c);
        const float2 bm = *reinterpret_cast<const float2*>(fp + xm * 64 + c);
        const float2 b0 = *reinterpret_cast<const float2*>(fp + x  * 64 + c);
        const float2 bp = *reinterpret_cast<const float2*>(fp + xp * 64 + c);
        const float2 fxm = *reinterpret_cast<const float2*>(P0 + xm * 64 + c);
        const float2 fxp = *reinterpret_cast<const float2*>(P0 + xp * 64 + c);

        float dyx = (bm.x + 2.f * b0.x + bp.x) - (am.x + 2.f * a0.x + ap.x);
        float dyy = (bm.y + 2.f * b0.y + bp.y) - (am.y + 2.f * a0.y + ap.y);
        float dxx = (ap.x - am.x) + 2.f * (fxp.x - fxm.x) + (bp.x - bm.x);
        float dxy = (ap.y - am.y) + 2.f * (fxp.y - fxm.y) + (bp.y - bm.y);

        float bxx = (2.f * DT) / (0.25f * dyx * dyx + 1.f);
        float bxy = (2.f * DT) / (0.25f * dyy * dyy + 1.f);
        float byx = (2.f * DT) / (0.25f * dxx * dxx + 1.f);
        float byy = (2.f * DT) / (0.25f * dxy * dxy + 1.f);
        *reinterpret_cast<float2*>(BX + i) = make_float2(bxx, bxy);
        *reinterpret_cast<float2*>(BY + i) = make_float2(byx, byy);

        cdr[j] = make_float2(1.f / (1.f + bxx + byx), 1.f / (1.f + bxy + byy));
        axr[j] = make_float2(DT * g2.x, DT * g2.y);
        cfr[j] = make_float2(2.f * DT * f2.x, 2.f * DT * f2.y);
        hprev[j] = f2;
        hcur[j]  = f2;

        const int ixm = (i + 8192 - 64) & 8191;
        const int ixp = (i + 64) & 8191;
        const float2 gxm = *reinterpret_cast<const float2*>(P1 + ixm);
        const float2 gxp = *reinterpret_cast<const float2*>(P1 + ixp);
        const float gcm = P1[(i & ~63) | ((c + 63) & 63)];
        const float gcp = P1[(i & ~63) | ((c + 2) & 63)];
        E2r[j].x = DT * ((gxm.x - gxp.x) + (gcm - g2.y));
        E2r[j].y = DT * ((gxm.y - gxp.y) + (g2.x - gcp));
    }
    __syncthreads();

#pragma unroll
    for (int k = 0; k < 5; ++k) {
        float* rb = (k & 1) ? P1 : P0;
        float* wb = (k & 1) ? P0 : P1;
#pragma unroll
        for (int j = 0; j < 8; ++j) {
            const int i = (tid + j * 512) * 2;
            const int ixm = (i + 8192 - 64) & 8191;
            const int ixp = (i + 64) & 8191;
            const float2 bx2 = *reinterpret_cast<const float2*>(BX + i);
            const float2 by2 = *reinterpret_cast<const float2*>(BY + i);
            const float2 rxm = *reinterpret_cast<const float2*>(rb + ixm);
            const float2 rxp = *reinterpret_cast<const float2*>(rb + ixp);
            const float rcm = rb[(i & ~63) | ((c + 63) & 63)];
            const float rcp = rb[(i & ~63) | ((c + 2) & 63)];
            const float2 hc = hcur[j];
            const float2 ax = axr[j];

            float s0 = (1.f - bx2.x - by2.x) * hprev[j].x;
            s0 = fmaf(-E2r[j].x, hc.x, s0);
            s0 = fmaf(bx2.x, rxm.x + rxp.x, s0);
            s0 = fmaf(ax.x,  rxp.x - rxm.x, s0);
            s0 = fmaf(by2.x, rcm + hc.y, s0);
            s0 = fmaf(ax.x,  hc.y - rcm, s0);
            s0 = (s0 + cfr[j].x) * cdr[j].x;

            float s1 = (1.f - bx2.y - by2.y) * hprev[j].y;
            s1 = fmaf(-E2r[j].y, hc.y, s1);
            s1 = fmaf(bx2.y, rxm.y + rxp.y, s1);
            s1 = fmaf(ax.y,  rxp.y - rxm.y, s1);
            s1 = fmaf(by2.y, hc.x + rcp, s1);
            s1 = fmaf(ax.y,  rcp - hc.x, s1);
            s1 = (s1 + cfr[j].y) * cdr[j].y;

            hprev[j] = hc;
            hcur[j]  = make_float2(s0, s1);
            if (k < 4) *reinterpret_cast<float2*>(wb + i) = hcur[j];
        }
        if (k < 4) __syncthreads();
    }

    float* o = outh + rowbase;
#pragma unroll
    for (int j = 0; j < 8; ++j) {
        const int i = (tid + j * 512) * 2;
        float2 r = make_float2(fmaxf(fmaf(hcur[j].x, sc2.x, sh2.x), 0.f),
                               fmaxf(fmaf(hcur[j].y, sc2.y, sh2.y), 0.f));
        *reinterpret_cast<float2*>(o + i) = r;
    }
}

// ===========================================================================
extern "C" void kernel_launch(void* const* d_in, const int* in_sizes, int n_in,
                              void* d_out, int out_size)
{
    const float* x   = (const float*)d_in[0];
    const float* f_w = (const float*)d_in[1];
    const float* g_w = (const float*)d_in[2];
    const float* bnf_gamma = (const float*)d_in[3];
    const float* bnf_beta  = (const float*)d_in[4];
    const float* bnf_mean  = (const float*)d_in[5];
    const float* bnf_var   = (const float*)d_in[6];
    const float* bng_gamma = (const float*)d_in[7];
    const float* bng_beta  = (const float*)d_in[8];
    const float* bng_mean  = (const float*)d_in[9];
    const float* bng_var   = (const float*)d_in[10];
    const float* bno_gamma = (const float*)d_in[11];
    const float* bno_beta  = (const float*)d_in[12];
    const float* bno_mean  = (const float*)d_in[13];
    const float* bno_var   = (const float*)d_in[14];

    float* out = (float*)d_out;            // [0:N) = h, [N:2N) = g

    float* fptr = nullptr;
    cudaGetSymbolAddress((void**)&fptr, d_f_buf);
    __nv_bfloat16* wptr = nullptr;
    cudaGetSymbolAddress((void**)&wptr, d_wbf);

    cudaFuncSetAttribute(conv_mma,
                         cudaFuncAttributeMaxDynamicSharedMemorySize, CONV_SMEM_BYTES);
    cudaFuncSetAttribute(diffuse_fused,
                         cudaFuncAttributeMaxDynamicSharedMemorySize, DIFF_SMEM_BYTES);

    // 1) weight transform (both convs)
    prep_weights<<<288, 256>>>(f_w, g_w);

    dim3 cgrid(H / 2, B);

    // 2) f = conv(relu(bn_f(x)), f_w)
    conv_mma<<<cgrid, CT, CONV_SMEM_BYTES>>>(
        x, wptr, bnf_gamma, bnf_beta, bnf_mean, bnf_var, fptr);

    // 3) g = conv(relu(bn_g(f)), g_w) -> d_out[N:2N)
    conv_mma<<<cgrid, CT, CONV_SMEM_BYTES>>>(
        fptr, wptr + 3 * B_TY, bng_gamma, bng_beta, bng_mean, bng_var, out + NTOT);

    // 4) fused sobel + coefficients + 5 diffusion iters + bn_o/relu -> d_out[0:N)
    dim3 dgrid(H, B);
    diffuse_fused<<<dgrid, 512, DIFF_SMEM_BYTES>>>(
        fptr, out, out + NTOT, bno_gamma, bno_beta, bno_mean, bno_var);
}